// round 16
// baseline (speedup 1.0000x reference)
#include <cuda_runtime.h>
#include <cuda_bf16.h>
#include <cstdint>

#define K_DIM 2048
#define INV_F (1.0f / 2048.0f)
#define M_TOTAL 16384
#define N_PAD 1024
#define BM 128
#define BN 128
#define BK 64                               // bf16 per stage (128 bytes/row)
#define STAGES 3
#define SA_BYTES 144                        // 128B data + 16B pad: conflict-free
#define TILE_BYTES (128 * SA_BYTES)         // 18432 per operand tile
#define STAGE_BYTES (2 * TILE_BYTES)        // 36864
#define DYN_SMEM (STAGES * STAGE_BYTES)     // 110592 (2 CTAs/SM)

// Scratch (no device allocation allowed): bf16 operands + exact fp32 norms.
__device__ __align__(16) __nv_bfloat16 g_xb[(size_t)M_TOTAL * K_DIM];
__device__ __align__(16) __nv_bfloat16 g_wb[(size_t)N_PAD * K_DIM];
__device__ float g_x2[M_TOTAL];
__device__ float g_w2[N_PAD];
// Completion counters, monotonic across graph replays (re-conversion is idempotent).
__device__ int g_xcnt[M_TOTAL / BM];
__device__ int g_wcnt[N_PAD / BN];

__device__ __forceinline__ uint32_t smem_u32(const void* p) {
    return (uint32_t)__cvta_generic_to_shared(p);
}

__device__ __forceinline__ int ld_acq(const int* p) {
    int v;
    asm volatile("ld.acquire.gpu.global.s32 %0, [%1];" : "=r"(v) : "l"(p));
    return v;
}

// Warp-converged mbarrier phase-parity wait (acquire).
__device__ __forceinline__ void mb_wait(uint32_t addr, int parity) {
    asm volatile(
        "{\n\t.reg .pred P;\n"
        "W%=:\n\t"
        "mbarrier.try_wait.parity.acquire.cta.shared::cta.b64 P, [%0], %1, 0x989680;\n\t"
        "@!P bra W%=;\n\t"
        "}" :: "r"(addr), "r"(parity) : "memory");
}

__device__ __forceinline__ void ldm_x4(uint32_t* r, uint32_t addr) {
    asm volatile("ldmatrix.sync.aligned.m8n8.x4.shared.b16 {%0,%1,%2,%3}, [%4];"
                 : "=r"(r[0]), "=r"(r[1]), "=r"(r[2]), "=r"(r[3]) : "r"(addr));
}

__device__ __forceinline__ void mma_bf16(float* d, const uint32_t* a, const uint32_t* b) {
    asm volatile(
        "mma.sync.aligned.m16n8k16.row.col.f32.bf16.bf16.f32 "
        "{%0,%1,%2,%3}, {%4,%5,%6,%7}, {%8,%9}, {%0,%1,%2,%3};"
        : "+f"(d[0]), "+f"(d[1]), "+f"(d[2]), "+f"(d[3])
        : "r"(a[0]), "r"(a[1]), "r"(a[2]), "r"(a[3]), "r"(b[0]), "r"(b[1]));
}

// ---- convert 4 consecutive rows (block-wide): fp32 -> bf16 + exact fp32 sumsq ----
__device__ void conv4(const float* __restrict__ src_base, __nv_bfloat16* dst_base,
                      float* norm_base, int nvalid, int tid) {
    __shared__ float cred4[8][4];
    const float4* src = reinterpret_cast<const float4*>(src_base);
    uint2* dst = reinterpret_cast<uint2*>(dst_base);
    float4 v[8];
#pragma unroll
    for (int i = 0; i < 8; ++i) {
        if ((i >> 1) < nvalid) v[i] = src[tid + i * 256];
        else                   v[i] = make_float4(0.f, 0.f, 0.f, 0.f);
    }
    float part[4] = {0.f, 0.f, 0.f, 0.f};
#pragma unroll
    for (int i = 0; i < 8; ++i) {
        part[i >> 1] += v[i].x * v[i].x + v[i].y * v[i].y +
                        v[i].z * v[i].z + v[i].w * v[i].w;
        __nv_bfloat162 p0 = __float22bfloat162_rn(make_float2(v[i].x, v[i].y));
        __nv_bfloat162 p1 = __float22bfloat162_rn(make_float2(v[i].z, v[i].w));
        uint2 o;
        o.x = *reinterpret_cast<uint32_t*>(&p0);
        o.y = *reinterpret_cast<uint32_t*>(&p1);
        dst[tid + i * 256] = o;
    }
#pragma unroll
    for (int o2 = 16; o2 > 0; o2 >>= 1)
#pragma unroll
        for (int r = 0; r < 4; ++r)
            part[r] += __shfl_xor_sync(0xffffffffu, part[r], o2);
    if ((tid & 31) == 0) {
        int wp = tid >> 5;
#pragma unroll
        for (int r = 0; r < 4; ++r) cred4[wp][r] = part[r];
    }
    __syncthreads();
    if (tid < 4) {
        float t = 0.f;
#pragma unroll
        for (int wp = 0; wp < 8; ++wp) t += cred4[wp][tid];
        norm_base[tid] = t;
    }
    __syncthreads();
}

// ---- convert 8 consecutive rows (block-wide), MLP=16 ----
__device__ void conv8(const float* __restrict__ src_base, __nv_bfloat16* dst_base,
                      float* norm_base, int tid) {
    __shared__ float cred[8][8];
    const float4* src = reinterpret_cast<const float4*>(src_base);
    uint2* dst = reinterpret_cast<uint2*>(dst_base);
    float4 v[16];
#pragma unroll
    for (int i = 0; i < 16; ++i) v[i] = src[tid + i * 256];
    float part[8];
#pragma unroll
    for (int r = 0; r < 8; ++r) part[r] = 0.f;
#pragma unroll
    for (int i = 0; i < 16; ++i) {
        part[i >> 1] += v[i].x * v[i].x + v[i].y * v[i].y +
                        v[i].z * v[i].z + v[i].w * v[i].w;
        __nv_bfloat162 p0 = __float22bfloat162_rn(make_float2(v[i].x, v[i].y));
        __nv_bfloat162 p1 = __float22bfloat162_rn(make_float2(v[i].z, v[i].w));
        uint2 o;
        o.x = *reinterpret_cast<uint32_t*>(&p0);
        o.y = *reinterpret_cast<uint32_t*>(&p1);
        dst[tid + i * 256] = o;
    }
#pragma unroll
    for (int o2 = 16; o2 > 0; o2 >>= 1)
#pragma unroll
        for (int r = 0; r < 8; ++r)
            part[r] += __shfl_xor_sync(0xffffffffu, part[r], o2);
    if ((tid & 31) == 0) {
        int wp = tid >> 5;
#pragma unroll
        for (int r = 0; r < 8; ++r) cred[wp][r] = part[r];
    }
    __syncthreads();
    if (tid < 8) {
        float t = 0.f;
#pragma unroll
        for (int wp = 0; wp < 8; ++wp) t += cred[wp][tid];
        norm_base[tid] = t;
    }
    __syncthreads();
}

// ---- stage producer: 8 cp.asyncs per thread + per-thread noinc arrive on full[s] ----
__device__ __forceinline__ void load_stage(uint32_t sb, int kt, int m0, int n0,
                                           int tid, uint32_t fullbar) {
    const __nv_bfloat16* xa = g_xb + (size_t)m0 * K_DIM + kt * BK;
    const __nv_bfloat16* wb = g_wb + (size_t)n0 * K_DIM + kt * BK;
#pragma unroll
    for (int i = 0; i < 8; ++i) {
        int idx = tid + i * 256;                 // 0..2047
        int op = idx >> 10;                      // 0 = A, 1 = B
        int r = (idx >> 3) & 127;
        int c = idx & 7;
        uint32_t dst = sb + (uint32_t)op * TILE_BYTES + (uint32_t)(r * SA_BYTES + c * 16);
        const __nv_bfloat16* src = (op ? wb : xa) + (size_t)r * K_DIM + c * 8;
        asm volatile("cp.async.cg.shared.global [%0], [%1], 16;"
                     :: "r"(dst), "l"(src) : "memory");
    }
    asm volatile("cp.async.mbarrier.arrive.noinc.shared::cta.b64 [%0];"
                 :: "r"(fullbar) : "memory");
}

// ---- fused kernel: self-service convert + spin + mbarrier-pipelined GEMM ----
// out[m,n] = -(x2[m] - 2*sum_k X[m,k]W[n,k] + w2[n]) / F

__global__ void __launch_bounds__(256, 2) fused_kernel(const float* __restrict__ x,
                                                       const float* __restrict__ w,
                                                       float* __restrict__ out, int N) {
    extern __shared__ __align__(16) char dyn_smem[];
    __shared__ float s_x2[BM];
    __shared__ float s_w2[BN];
    __shared__ __align__(8) uint64_t s_full[STAGES];
    __shared__ __align__(8) uint64_t s_empty[STAGES];

    const uint32_t base = smem_u32(dyn_smem);
    const int tid = threadIdx.x;
    const int wid = tid >> 5, lid = tid & 31;
    const int bid = blockIdx.x + 8 * blockIdx.y;
    const int m0 = blockIdx.y * BM;
    const int n0 = blockIdx.x * BN;
    const int mw = (wid >> 2) * 64;
    const int nw = (wid & 3) * 32;

    if (tid == 0) {
#pragma unroll
        for (int s = 0; s < STAGES; ++s) {
            asm volatile("mbarrier.init.shared.b64 [%0], %1;"
                         :: "r"(smem_u32(&s_full[s])), "r"(256) : "memory");
            asm volatile("mbarrier.init.shared.b64 [%0], %1;"
                         :: "r"(smem_u32(&s_empty[s])), "r"(8) : "memory");
        }
    }

    // --- Phase 1a: w conversion spread over bids 0..255 (first wave), 4 rows each.
    if (bid < N_PAD / 4) {
        int r0 = bid * 4;
        int nv = N - r0;
        nv = nv < 0 ? 0 : (nv > 4 ? 4 : nv);
        conv4(w + (size_t)r0 * K_DIM, g_wb + (size_t)r0 * K_DIM, &g_w2[r0], nv, tid);
        if (tid == 0) {
            __threadfence();
            atomicAdd(&g_wcnt[r0 >> 7], 4);
        }
    }

    // --- Phase 1b: each CTA converts its own 16 x rows (8 CTAs cover m-block y).
    {
        int xr0 = m0 + blockIdx.x * 16;
#pragma unroll
        for (int it = 0; it < 2; ++it) {
            int r0 = xr0 + it * 8;
            conv8(x + (size_t)r0 * K_DIM, g_xb + (size_t)r0 * K_DIM, &g_x2[r0], tid);
        }
        if (tid == 0) {
            __threadfence();
            atomicAdd(&g_xcnt[blockIdx.y], 16);
        }
    }

    // --- Phase 2: wait for operand blocks.
    if (tid == 0) {
        while (ld_acq(&g_wcnt[blockIdx.x]) < 128) __nanosleep(64);
        while (ld_acq(&g_xcnt[blockIdx.y]) < 128) __nanosleep(64);
    }
    __syncthreads();

    if (tid < BM) s_x2[tid] = g_x2[m0 + tid];
    else          s_w2[tid - BM] = g_w2[n0 + tid - BM];
    __syncthreads();   // s_x2/s_w2 + mbarrier init visible to all before loop/epilogue

    // Rotating stage state: slots (A,B,C) = stages (kt%3, kt+1, kt+2).
    uint32_t sbA = base, sbB = base + STAGE_BYTES, sbC = base + 2u * STAGE_BYTES;
    uint32_t fuA = smem_u32(&s_full[0]), fuB = smem_u32(&s_full[1]), fuC = smem_u32(&s_full[2]);
    uint32_t emA = smem_u32(&s_empty[0]), emB = smem_u32(&s_empty[1]), emC = smem_u32(&s_empty[2]);
    int fpA = 0, fpB = 0, fpC = 0;       // full parities
    int epA = 0, epB = 0, epC = 1;       // empty parities

    // Prologue: chunks 0,1 -> stages 0,1 (fresh stages, no empty wait).
    load_stage(sbA, 0, m0, n0, tid, fuA);
    load_stage(sbB, 1, m0, n0, tid, fuB);

    float acc[4][4][4] = {};

    const uint32_t a_lane = (uint32_t)((mw + (lid & 15)) * SA_BYTES + (lid >> 4) * 16);
    const uint32_t b_lane = (uint32_t)TILE_BYTES +
        (uint32_t)((nw + (lid & 7) + ((lid >> 4) << 3)) * SA_BYTES + ((lid >> 3) & 1) * 16);

    const int NITER = K_DIM / BK;  // 32
    for (int kt = 0; kt < NITER; ++kt) {
        int kl = kt + 2;
        if (kl < NITER) {
            mb_wait(emC, epC);                 // WAR: stage kt+2 drained by all warps
            load_stage(sbC, kl, m0, n0, tid, fuC);
        }

        mb_wait(fuA, fpA);                     // RAW: stage kt data landed
        const uint32_t al = sbA + a_lane, bl = sbA + b_lane;

#pragma unroll
        for (int ks = 0; ks < 4; ++ks) {
            uint32_t a_frag[4][4], b_frag[2][4];
#pragma unroll
            for (int mt = 0; mt < 4; ++mt)
                ldm_x4(a_frag[mt], al + (uint32_t)(mt * 16 * SA_BYTES + ks * 32));
#pragma unroll
            for (int nt = 0; nt < 2; ++nt)
                ldm_x4(b_frag[nt], bl + (uint32_t)(nt * 16 * SA_BYTES + ks * 32));
#pragma unroll
            for (int mt = 0; mt < 4; ++mt)
#pragma unroll
                for (int nt = 0; nt < 4; ++nt)
                    mma_bf16(acc[mt][nt], a_frag[mt], &b_frag[nt >> 1][(nt & 1) * 2]);
        }
        __syncwarp();
        if (lid == 0)
            asm volatile("mbarrier.arrive.shared.b64 _, [%0];" :: "r"(emA) : "memory");

        // Rotate slots: (A,B,C) <- (B, C, A), flipping consumed/produced parities.
        uint32_t tu;
        int tp;
        tu = sbA; sbA = sbB; sbB = sbC; sbC = tu;
        tu = fuA; fuA = fuB; fuB = fuC; fuC = tu;
        tu = emA; emA = emB; emB = emC; emC = tu;
        tp = fpA ^ 1; fpA = fpB; fpB = fpC; fpC = tp;
        tp = epA;     epA = epB; epB = epC ^ 1; epC = tp;
    }

    // Epilogue: fused norms; lane l owns rows q, q+8 and col pair 2*(l%4).
    const int q = lid >> 2, rr = lid & 3;
#pragma unroll
    for (int mt = 0; mt < 4; ++mt) {
        int r0 = mw + mt * 16 + q;
        float x2a = s_x2[r0], x2b = s_x2[r0 + 8];
        float* orow0 = out + (size_t)(m0 + r0) * N;
        float* orow1 = orow0 + (size_t)8 * N;
#pragma unroll
        for (int nt = 0; nt < 4; ++nt) {
            int cl = nw + nt * 8 + 2 * rr;
            int col = n0 + cl;
            if (col < N) {
                float w2a = s_w2[cl], w2b = s_w2[cl + 1];
                float2 v0, v1;
                v0.x = (2.0f * INV_F) * acc[mt][nt][0] - (x2a + w2a) * INV_F;
                v0.y = (2.0f * INV_F) * acc[mt][nt][1] - (x2a + w2b) * INV_F;
                v1.x = (2.0f * INV_F) * acc[mt][nt][2] - (x2b + w2a) * INV_F;
                v1.y = (2.0f * INV_F) * acc[mt][nt][3] - (x2b + w2b) * INV_F;
                *reinterpret_cast<float2*>(orow0 + col) = v0;
                *reinterpret_cast<float2*>(orow1 + col) = v1;
            }
        }
    }
}

extern "C" void kernel_launch(void* const* d_in, const int* in_sizes, int n_in,
                              void* d_out, int out_size) {
    const float* x = (const float*)d_in[0];
    const float* w = (const float*)d_in[1];
    float* out = (float*)d_out;
    int N = in_sizes[1] / K_DIM;   // 1000

    cudaFuncSetAttribute(fused_kernel,
                         cudaFuncAttributeMaxDynamicSharedMemorySize, DYN_SMEM);
    fused_kernel<<<dim3(N_PAD / BN, M_TOTAL / BM), 256, DYN_SMEM>>>(x, w, out, N);
}

// round 17
// speedup vs baseline: 1.0080x; 1.0080x over previous
#include <cuda_runtime.h>
#include <cuda_bf16.h>
#include <cstdint>

#define K_DIM 2048
#define INV_F (1.0f / 2048.0f)
#define M_TOTAL 16384
#define N_PAD 1024
#define BM 128
#define BN 128
#define BK 64                               // bf16 per stage (128 bytes/row)
#define STAGES 3
#define SA_BYTES 144                        // 128B data + 16B pad: conflict-free
#define TILE_BYTES (128 * SA_BYTES)         // 18432 per operand tile
#define STAGE_BYTES (2 * TILE_BYTES)        // 36864
#define DYN_SMEM (STAGES * STAGE_BYTES)     // 110592 (2 CTAs/SM)

// Scratch (no device allocation allowed): bf16 operands + exact fp32 norms.
__device__ __align__(16) __nv_bfloat16 g_xb[(size_t)M_TOTAL * K_DIM];
__device__ __align__(16) __nv_bfloat16 g_wb[(size_t)N_PAD * K_DIM];
__device__ float g_x2[M_TOTAL];
__device__ float g_w2[N_PAD];
// Completion counters, monotonic across graph replays (re-conversion is idempotent).
__device__ int g_xcnt[M_TOTAL / BM];
__device__ int g_wcnt[N_PAD / BN];

__device__ __forceinline__ uint32_t smem_u32(const void* p) {
    return (uint32_t)__cvta_generic_to_shared(p);
}

__device__ __forceinline__ int ld_acq(const int* p) {
    int v;
    asm volatile("ld.acquire.gpu.global.s32 %0, [%1];" : "=r"(v) : "l"(p));
    return v;
}

// Warp-converged mbarrier phase-parity wait (acquire).
__device__ __forceinline__ void mb_wait(uint32_t addr, int parity) {
    asm volatile(
        "{\n\t.reg .pred P;\n"
        "W%=:\n\t"
        "mbarrier.try_wait.parity.acquire.cta.shared::cta.b64 P, [%0], %1, 0x989680;\n\t"
        "@!P bra W%=;\n\t"
        "}" :: "r"(addr), "r"(parity) : "memory");
}

__device__ __forceinline__ void ldm_x4(uint32_t* r, uint32_t addr) {
    asm volatile("ldmatrix.sync.aligned.m8n8.x4.shared.b16 {%0,%1,%2,%3}, [%4];"
                 : "=r"(r[0]), "=r"(r[1]), "=r"(r[2]), "=r"(r[3]) : "r"(addr));
}

__device__ __forceinline__ void mma_bf16(float* d, const uint32_t* a, const uint32_t* b) {
    asm volatile(
        "mma.sync.aligned.m16n8k16.row.col.f32.bf16.bf16.f32 "
        "{%0,%1,%2,%3}, {%4,%5,%6,%7}, {%8,%9}, {%0,%1,%2,%3};"
        : "+f"(d[0]), "+f"(d[1]), "+f"(d[2]), "+f"(d[3])
        : "r"(a[0]), "r"(a[1]), "r"(a[2]), "r"(a[3]), "r"(b[0]), "r"(b[1]));
}

// ---- convert 8 consecutive rows (block-wide): fp32 -> bf16 + exact fp32 sumsq ----
// 16 float4 loads in flight per thread (MLP=16). Rows >= nvalid written as zeros.
__device__ void conv8(const float* __restrict__ src_base, __nv_bfloat16* dst_base,
                      float* norm_base, int nvalid, int tid) {
    __shared__ float cred[8][8];
    const float4* src = reinterpret_cast<const float4*>(src_base);
    uint2* dst = reinterpret_cast<uint2*>(dst_base);
    float4 v[16];
#pragma unroll
    for (int i = 0; i < 16; ++i) {
        if ((i >> 1) < nvalid) v[i] = src[tid + i * 256];   // row_local = i>>1
        else                   v[i] = make_float4(0.f, 0.f, 0.f, 0.f);
    }
    float part[8];
#pragma unroll
    for (int r = 0; r < 8; ++r) part[r] = 0.f;
#pragma unroll
    for (int i = 0; i < 16; ++i) {
        part[i >> 1] += v[i].x * v[i].x + v[i].y * v[i].y +
                        v[i].z * v[i].z + v[i].w * v[i].w;
        __nv_bfloat162 p0 = __float22bfloat162_rn(make_float2(v[i].x, v[i].y));
        __nv_bfloat162 p1 = __float22bfloat162_rn(make_float2(v[i].z, v[i].w));
        uint2 o;
        o.x = *reinterpret_cast<uint32_t*>(&p0);
        o.y = *reinterpret_cast<uint32_t*>(&p1);
        dst[tid + i * 256] = o;
    }
#pragma unroll
    for (int o2 = 16; o2 > 0; o2 >>= 1)
#pragma unroll
        for (int r = 0; r < 8; ++r)
            part[r] += __shfl_xor_sync(0xffffffffu, part[r], o2);
    if ((tid & 31) == 0) {
        int wp = tid >> 5;
#pragma unroll
        for (int r = 0; r < 8; ++r) cred[wp][r] = part[r];
    }
    __syncthreads();
    if (tid < 8) {
        float t = 0.f;
#pragma unroll
        for (int wp = 0; wp < 8; ++wp) t += cred[wp][tid];
        norm_base[tid] = t;
    }
    __syncthreads();
}

// ---- stage producer: 8 cp.asyncs per thread + per-thread noinc arrive on full[s] ----
__device__ __forceinline__ void load_stage(uint32_t sb, int kt, int m0, int n0,
                                           int tid, uint32_t fullbar) {
    const __nv_bfloat16* xa = g_xb + (size_t)m0 * K_DIM + kt * BK;
    const __nv_bfloat16* wb = g_wb + (size_t)n0 * K_DIM + kt * BK;
#pragma unroll
    for (int i = 0; i < 8; ++i) {
        int idx = tid + i * 256;                 // 0..2047
        int op = idx >> 10;                      // 0 = A, 1 = B
        int r = (idx >> 3) & 127;
        int c = idx & 7;
        uint32_t dst = sb + (uint32_t)op * TILE_BYTES + (uint32_t)(r * SA_BYTES + c * 16);
        const __nv_bfloat16* src = (op ? wb : xa) + (size_t)r * K_DIM + c * 8;
        asm volatile("cp.async.cg.shared.global [%0], [%1], 16;"
                     :: "r"(dst), "l"(src) : "memory");
    }
    asm volatile("cp.async.mbarrier.arrive.noinc.shared::cta.b64 [%0];"
                 :: "r"(fullbar) : "memory");
}

// ---- fused kernel: self-service convert + spin + mbarrier-pipelined GEMM ----
// out[m,n] = -(x2[m] - 2*sum_k X[m,k]W[n,k] + w2[n]) / F

__global__ void __launch_bounds__(256, 2) fused_kernel(const float* __restrict__ x,
                                                       const float* __restrict__ w,
                                                       float* __restrict__ out, int N) {
    extern __shared__ __align__(16) char dyn_smem[];
    __shared__ float s_x2[BM];
    __shared__ float s_w2[BN];
    __shared__ __align__(8) uint64_t s_full[STAGES];
    __shared__ __align__(8) uint64_t s_empty[STAGES];

    const uint32_t base = smem_u32(dyn_smem);
    const int tid = threadIdx.x;
    const int wid = tid >> 5, lid = tid & 31;
    const int bid = blockIdx.x + 8 * blockIdx.y;
    const int m0 = blockIdx.y * BM;
    const int n0 = blockIdx.x * BN;
    const int mw = (wid >> 2) * 64;
    const int nw = (wid & 3) * 32;

    if (tid == 0) {
#pragma unroll
        for (int s = 0; s < STAGES; ++s) {
            asm volatile("mbarrier.init.shared.b64 [%0], %1;"
                         :: "r"(smem_u32(&s_full[s])), "r"(256) : "memory");
            asm volatile("mbarrier.init.shared.b64 [%0], %1;"
                         :: "r"(smem_u32(&s_empty[s])), "r"(8) : "memory");
        }
    }

    // --- Phase 1a: w conversion by bids 0..127 (first wave), 8 rows each.
    if (bid < N_PAD / 8) {
        int r0 = bid * 8;
        int nv = N - r0;
        nv = nv < 0 ? 0 : (nv > 8 ? 8 : nv);
        conv8(w + (size_t)r0 * K_DIM, g_wb + (size_t)r0 * K_DIM, &g_w2[r0], nv, tid);
        if (tid == 0) {
            __threadfence();
            atomicAdd(&g_wcnt[r0 >> 7], 8);
        }
    }

    // --- Phase 1b: each CTA converts its own 16 x rows (8 CTAs cover m-block y).
    {
        int xr0 = m0 + blockIdx.x * 16;
#pragma unroll
        for (int it = 0; it < 2; ++it) {
            int r0 = xr0 + it * 8;
            conv8(x + (size_t)r0 * K_DIM, g_xb + (size_t)r0 * K_DIM, &g_x2[r0], 8, tid);
        }
        if (tid == 0) {
            __threadfence();
            atomicAdd(&g_xcnt[blockIdx.y], 16);
        }
    }

    // --- Phase 2: wait for operand blocks (x first: it resolves last; two
    // spinner threads so both counters are polled concurrently).
    if (tid == 0) {
        while (ld_acq(&g_xcnt[blockIdx.y]) < 128) __nanosleep(64);
    } else if (tid == 32) {
        while (ld_acq(&g_wcnt[blockIdx.x]) < 128) __nanosleep(64);
    }
    __syncthreads();

    if (tid < BM) s_x2[tid] = g_x2[m0 + tid];
    else          s_w2[tid - BM] = g_w2[n0 + tid - BM];
    __syncthreads();   // s_x2/s_w2 + mbarrier init visible to all before loop/epilogue

    // Rotating stage state: slots (A,B,C) = stages (kt%3, kt+1, kt+2).
    uint32_t sbA = base, sbB = base + STAGE_BYTES, sbC = base + 2u * STAGE_BYTES;
    uint32_t fuA = smem_u32(&s_full[0]), fuB = smem_u32(&s_full[1]), fuC = smem_u32(&s_full[2]);
    uint32_t emA = smem_u32(&s_empty[0]), emB = smem_u32(&s_empty[1]), emC = smem_u32(&s_empty[2]);
    int fpA = 0, fpB = 0, fpC = 0;       // full parities
    int epA = 0, epB = 0, epC = 1;       // empty parities

    // Prologue: chunks 0,1 -> stages 0,1 (fresh stages, no empty wait).
    load_stage(sbA, 0, m0, n0, tid, fuA);
    load_stage(sbB, 1, m0, n0, tid, fuB);

    float acc[4][4][4] = {};

    const uint32_t a_lane = (uint32_t)((mw + (lid & 15)) * SA_BYTES + (lid >> 4) * 16);
    const uint32_t b_lane = (uint32_t)TILE_BYTES +
        (uint32_t)((nw + (lid & 7) + ((lid >> 4) << 3)) * SA_BYTES + ((lid >> 3) & 1) * 16);

    const int NITER = K_DIM / BK;  // 32
    for (int kt = 0; kt < NITER; ++kt) {
        int kl = kt + 2;
        if (kl < NITER) {
            mb_wait(emC, epC);                 // WAR: stage kt+2 drained by all warps
            load_stage(sbC, kl, m0, n0, tid, fuC);
        }

        mb_wait(fuA, fpA);                     // RAW: stage kt data landed
        const uint32_t al = sbA + a_lane, bl = sbA + b_lane;

#pragma unroll
        for (int ks = 0; ks < 4; ++ks) {
            uint32_t a_frag[4][4], b_frag[2][4];
#pragma unroll
            for (int mt = 0; mt < 4; ++mt)
                ldm_x4(a_frag[mt], al + (uint32_t)(mt * 16 * SA_BYTES + ks * 32));
#pragma unroll
            for (int nt = 0; nt < 2; ++nt)
                ldm_x4(b_frag[nt], bl + (uint32_t)(nt * 16 * SA_BYTES + ks * 32));
#pragma unroll
            for (int mt = 0; mt < 4; ++mt)
#pragma unroll
                for (int nt = 0; nt < 4; ++nt)
                    mma_bf16(acc[mt][nt], a_frag[mt], &b_frag[nt >> 1][(nt & 1) * 2]);
        }
        __syncwarp();
        if (lid == 0)
            asm volatile("mbarrier.arrive.shared.b64 _, [%0];" :: "r"(emA) : "memory");

        // Rotate slots: (A,B,C) <- (B, C, A), flipping consumed/produced parities.
        uint32_t tu;
        int tp;
        tu = sbA; sbA = sbB; sbB = sbC; sbC = tu;
        tu = fuA; fuA = fuB; fuB = fuC; fuC = tu;
        tu = emA; emA = emB; emB = emC; emC = tu;
        tp = fpA ^ 1; fpA = fpB; fpB = fpC; fpC = tp;
        tp = epA;     epA = epB; epB = epC ^ 1; epC = tp;
    }

    // Epilogue: fused norms; lane l owns rows q, q+8 and col pair 2*(l%4).
    const int q = lid >> 2, rr = lid & 3;
#pragma unroll
    for (int mt = 0; mt < 4; ++mt) {
        int r0 = mw + mt * 16 + q;
        float x2a = s_x2[r0], x2b = s_x2[r0 + 8];
        float* orow0 = out + (size_t)(m0 + r0) * N;
        float* orow1 = orow0 + (size_t)8 * N;
#pragma unroll
        for (int nt = 0; nt < 4; ++nt) {
            int cl = nw + nt * 8 + 2 * rr;
            int col = n0 + cl;
            if (col < N) {
                float w2a = s_w2[cl], w2b = s_w2[cl + 1];
                float2 v0, v1;
                v0.x = (2.0f * INV_F) * acc[mt][nt][0] - (x2a + w2a) * INV_F;
                v0.y = (2.0f * INV_F) * acc[mt][nt][1] - (x2a + w2b) * INV_F;
                v1.x = (2.0f * INV_F) * acc[mt][nt][2] - (x2b + w2a) * INV_F;
                v1.y = (2.0f * INV_F) * acc[mt][nt][3] - (x2b + w2b) * INV_F;
                *reinterpret_cast<float2*>(orow0 + col) = v0;
                *reinterpret_cast<float2*>(orow1 + col) = v1;
            }
        }
    }
}

extern "C" void kernel_launch(void* const* d_in, const int* in_sizes, int n_in,
                              void* d_out, int out_size) {
    const float* x = (const float*)d_in[0];
    const float* w = (const float*)d_in[1];
    float* out = (float*)d_out;
    int N = in_sizes[1] / K_DIM;   // 1000

    cudaFuncSetAttribute(fused_kernel,
                         cudaFuncAttributeMaxDynamicSharedMemorySize, DYN_SMEM);
    fused_kernel<<<dim3(N_PAD / BN, M_TOTAL / BM), 256, DYN_SMEM>>>(x, w, out, N);
}